// round 14
// baseline (speedup 1.0000x reference)
#include <cuda_runtime.h>
#include <cuda_fp16.h>
#include <math.h>
#include <stdint.h>

#define N_NODES 131072
#define N_DST   16384
#define DEG     16
#define N_EDGES (N_DST*DEG)
#define HID     256

// ---------------- global scratch (device globals: no runtime alloc) --------
__device__ __align__(16) __half g_m2m[(size_t)N_DST * 256];     // m2mean
__device__ __align__(16) __half g_hh [(size_t)N_NODES * 256];
__device__ __align__(16) __half g_eaH[(size_t)N_NODES * 512];
__device__ __align__(16) float  g_eb [(size_t)N_DST   * 512];
__device__ __align__(16) __half g_w2h [256*256];
__device__ __align__(16) __half g_w3h [256*256];
__device__ __align__(16) __half g_mw1h[512*512];
__device__ __align__(16) __half g_mw2h[256*512];
__device__ __align__(16) __half g_mw3h[256*256];
__device__ int g_is64;

__device__ __forceinline__ float gelu_exact(float x){
    return 0.5f * x * (1.0f + erff(x * 0.70710678118654752f));
}
__device__ __forceinline__ uint32_t smem_u32(const void* p){
    uint32_t a;
    asm("{ .reg .u64 t; cvta.to.shared.u64 t, %1; cvt.u32.u64 %0, t; }" : "=r"(a) : "l"(p));
    return a;
}
__device__ __forceinline__ void mma16(float* c, const uint32_t* a, const uint32_t* b){
    asm volatile("mma.sync.aligned.m16n8k16.row.col.f32.f16.f16.f32 "
        "{%0,%1,%2,%3}, {%4,%5,%6,%7}, {%8,%9}, {%0,%1,%2,%3};"
        : "+f"(c[0]), "+f"(c[1]), "+f"(c[2]), "+f"(c[3])
        : "r"(a[0]), "r"(a[1]), "r"(a[2]), "r"(a[3]), "r"(b[0]), "r"(b[1]));
}
__device__ __forceinline__ void ldsm4(uint32_t& r0, uint32_t& r1, uint32_t& r2, uint32_t& r3,
                                      uint32_t addr){
    asm volatile("ldmatrix.sync.aligned.m8n8.x4.shared.b16 {%0,%1,%2,%3}, [%4];"
        : "=r"(r0), "=r"(r1), "=r"(r2), "=r"(r3) : "r"(addr));
}
#define CP16(dst, src) \
    asm volatile("cp.async.ca.shared.global [%0], [%1], 16;" :: "r"(dst), "l"(src) : "memory")
#define CP_COMMIT() asm volatile("cp.async.commit_group;" ::: "memory")
#define CP_WAIT2()  asm volatile("cp.async.wait_group 2;"  ::: "memory")
#define CP_WAIT1()  asm volatile("cp.async.wait_group 1;"  ::: "memory")

// ---------------------------------------------------------------------------
// one-shot fp16 conversion of all five weight matrices + edge-dtype detect
__global__ __launch_bounds__(256)
void f2h_all(const float* __restrict__ w2, const float* __restrict__ w3,
             const float* __restrict__ m1, const float* __restrict__ m2,
             const float* __restrict__ m3,
             __half* __restrict__ dw2, __half* __restrict__ dw3,
             __half* __restrict__ dm1, __half* __restrict__ dm2,
             __half* __restrict__ dm3, const int* __restrict__ me32)
{
    int i = blockIdx.x*256 + threadIdx.x;          // float4 index, total 147456
    if (i == 0) g_is64 = (me32[32] != 1) ? 1 : 0;
    const float* s; __half* d; int off;
    if      (i <  16384){ s = w2; d = dw2; off = i; }
    else if (i <  32768){ s = w3; d = dw3; off = i - 16384; }
    else if (i <  98304){ s = m1; d = dm1; off = i - 32768; }
    else if (i < 131072){ s = m2; d = dm2; off = i - 98304; }
    else                { s = m3; d = dm3; off = i - 131072; }
    float4 v = ((const float4*)s)[off];
    __half2 h0 = __floats2half2_rn(v.x, v.y), h1 = __floats2half2_rn(v.z, v.w);
    uint2 pk;
    pk.x = *reinterpret_cast<uint32_t*>(&h0);
    pk.y = *reinterpret_cast<uint32_t*>(&h1);
    ((uint2*)d)[off] = pk;
}

// ---------------------------------------------------------------------------
// fp16 mma.sync GEMM: C[M x Ntot] = epi(A[M x K] @ W[Ntot x K]^T + bias)
// Block 128x128, BK=32, 256 threads = 8 warps (4m x 2n), warp tile 32x64.
// 4-stage cp.async, 64KB smem, 2 CTAs/SM.  (R11 proven config)
// EPI: 0=fp32 store(+bias), 4=plain fp16.
// ---------------------------------------------------------------------------
#define GEMM_SMEM (64*1024)

template<int K, int EPI, bool HAS_BIAS>
__global__ __launch_bounds__(256, 2)
void gemm16(const __half* __restrict__ A, int lda,
            const __half* __restrict__ W, int ldw,
            const float* __restrict__ bias,
            void* __restrict__ Cout, int ldc)
{
    extern __shared__ char smem[];
    const int t    = threadIdx.x;
    const int lane = t & 31;
    const int w    = t >> 5;
    const int wm   = w >> 1, wn = w & 1;          // 4 x 2 warp grid
    const int gid  = lane >> 2, tig = lane & 3;
    const int m0   = blockIdx.x * 128;
    const int n0   = blockIdx.y * 128;
    const uint32_t sb = smem_u32(smem);

    uint32_t offA[2], offB[4];
    {
        const int l8 = lane & 7;
        const int h3 = (lane >> 3) & 1;
        const int h4 = lane >> 4;
        #pragma unroll
        for (int mi = 0; mi < 2; mi++){
            int rA = wm*32 + mi*16 + h3*8 + l8;
            int sw = (rA >> 1) & 3;
            offA[mi] = (uint32_t)(rA*64) + (uint32_t)((h4 ^ sw) << 4);
        }
        #pragma unroll
        for (int p = 0; p < 4; p++){
            int rB = wn*64 + p*16 + h4*8 + l8;
            int sw = (rB >> 1) & 3;
            offB[p] = (uint32_t)(rB*64) + (uint32_t)((h3 ^ sw) << 4);
        }
    }

    float acc[2][8][4];
    #pragma unroll
    for (int i = 0; i < 2; i++)
        #pragma unroll
        for (int j = 0; j < 8; j++)
            #pragma unroll
            for (int r = 0; r < 4; r++) acc[i][j][r] = 0.f;

    constexpr int NC = K / 32;

    auto produce = [&](int kc){
        const int st = kc & 3;
        #pragma unroll
        for (int it = 0; it < 2; it++){
            const int idx = it*256 + t, r = idx >> 2, c = idx & 3;
            uint32_t dst = sb + st*8192 + r*64 + (uint32_t)((c ^ ((r>>1)&3)) << 4);
            CP16(dst, (const void*)(A + (size_t)(m0 + r)*lda + kc*32 + c*8));
        }
        #pragma unroll
        for (int it = 0; it < 2; it++){
            const int idx = it*256 + t, rr = idx >> 2, cc = idx & 3;
            uint32_t db = sb + 32768 + st*8192 + rr*64 + (uint32_t)((cc ^ ((rr>>1)&3)) << 4);
            CP16(db, (const void*)(W + (size_t)(n0 + rr)*ldw + kc*32 + cc*8));
        }
        CP_COMMIT();
    };

    produce(0); produce(1); produce(2);

    #pragma unroll 1
    for (int kc = 0; kc < NC; kc++){
        CP_WAIT2();
        __syncthreads();
        const uint32_t aB = sb + (kc & 3)*8192;
        const uint32_t bB = sb + 32768u + (kc & 3)*8192;
        #pragma unroll
        for (int s = 0; s < 2; s++){
            const uint32_t sx = (uint32_t)s << 5;
            uint32_t afr[2][4], bfr[8][2];
            #pragma unroll
            for (int mi = 0; mi < 2; mi++)
                ldsm4(afr[mi][0], afr[mi][1], afr[mi][2], afr[mi][3],
                      aB + (offA[mi] ^ sx));
            #pragma unroll
            for (int p = 0; p < 4; p++)
                ldsm4(bfr[2*p][0], bfr[2*p][1], bfr[2*p+1][0], bfr[2*p+1][1],
                      bB + (offB[p] ^ sx));
            #pragma unroll
            for (int mi = 0; mi < 2; mi++)
                #pragma unroll
                for (int nj = 0; nj < 8; nj++)
                    mma16(acc[mi][nj], afr[mi], bfr[nj]);
        }
        if (kc + 3 < NC) produce(kc + 3); else CP_COMMIT();
    }

    // ---- epilogue ----
    #pragma unroll
    for (int mi = 0; mi < 2; mi++){
        const int r0 = m0 + wm*32 + mi*16 + gid;
        const int r1 = r0 + 8;
        #pragma unroll
        for (int nj = 0; nj < 8; nj++){
            const int cb = n0 + wn*64 + nj*8 + 2*tig;
            float v0 = acc[mi][nj][0], v1 = acc[mi][nj][1];
            float v2 = acc[mi][nj][2], v3 = acc[mi][nj][3];
            if (HAS_BIAS){
                const float b0 = bias[cb], b1 = bias[cb+1];
                v0 += b0; v1 += b1; v2 += b0; v3 += b1;
            }
            if (EPI == 0){
                float* C = (float*)Cout;
                *(float2*)(C + (size_t)r0*ldc + cb) = make_float2(v0, v1);
                *(float2*)(C + (size_t)r1*ldc + cb) = make_float2(v2, v3);
            } else {
                __half* C = (__half*)Cout;
                *(__half2*)(C + (size_t)r0*ldc + cb) = __floats2half2_rn(v0, v1);
                *(__half2*)(C + (size_t)r1*ldc + cb) = __floats2half2_rn(v2, v3);
            }
        }
    }
}

// ---------------------------------------------------------------------------
// Fused node-encoder kernel, 2 CTAs/SM: per block of 64 nodes (R11 proven):
//   phase 0: h1 = gelu(x @ W1^T + b1) computed in-producer  (K=3, smem-cached)
//   phase 1: h2 = gelu(h1 @ W2^T + b2)            (K=256)  -> SMEM
//   phase 2: hh = h2 @ W3^T + b3 + fourier(pos)   (K=256)  -> gmem fp16
// ---------------------------------------------------------------------------
#define FUSED_SMEM (64*1024)

__global__ __launch_bounds__(256, 2)
void node_fused(const float* __restrict__ xg,
                const float* __restrict__ w1g, const float* __restrict__ b1g,
                const __half* __restrict__ W2, const float* __restrict__ b2,
                const __half* __restrict__ W3, const float* __restrict__ b3,
                const float* __restrict__ pos, const float* __restrict__ bfour,
                __half* __restrict__ hh)
{
    extern __shared__ char smem[];
    __shared__ float sX[64*3];
    __shared__ float sW1[256*3];
    __shared__ float sB1[256];
    const int t    = threadIdx.x;
    const int lane = t & 31;
    const int w    = t >> 5;
    const int wm   = w >> 2, wn = w & 3;          // 2 x 4 warp grid
    const int gid  = lane >> 2, tig = lane & 3;
    const int m0   = blockIdx.x * 64;
    const uint32_t sb = smem_u32(smem);

    if (t < 192) sX[t] = xg[(size_t)m0*3 + t];
    for (int i = t; i < 768; i += 256) sW1[i] = w1g[i];
    sB1[t] = b1g[t];
    __syncthreads();

    uint32_t offA[2], offB[4], baseM[2];
    int swM[2];
    const int l8 = lane & 7;
    const int h3 = (lane >> 3) & 1;
    const int h4 = lane >> 4;
    #pragma unroll
    for (int mi = 0; mi < 2; mi++){
        int rA = wm*32 + mi*16 + h3*8 + l8;          // 0..63
        int sw = (rA >> 1) & 3;
        offA[mi] = (uint32_t)(rA*64) + (uint32_t)((h4 ^ sw) << 4);
        baseM[mi] = (uint32_t)(rA*512);
        swM[mi] = rA & 7;
    }
    #pragma unroll
    for (int p = 0; p < 4; p++){
        int rB = wn*64 + p*16 + h4*8 + l8;           // 0..255
        int sw = (rB >> 1) & 3;
        offB[p] = (uint32_t)(rB*64) + (uint32_t)((h3 ^ sw) << 4);
    }

    float acc[2][8][4];
    #pragma unroll
    for (int i = 0; i < 2; i++)
        #pragma unroll
        for (int j = 0; j < 8; j++)
            #pragma unroll
            for (int r = 0; r < 4; r++) acc[i][j][r] = 0.f;

    auto produce1 = [&](int kc, int st){
        const int r = t >> 2, c = t & 3;             // r: 0..63
        const int j0 = kc*32 + c*8;
        const float x0 = sX[r*3], x1 = sX[r*3+1], x2 = sX[r*3+2];
        uint4 pk;
        uint32_t* pw = (uint32_t*)&pk;
        #pragma unroll
        for (int jj = 0; jj < 4; jj++){
            const int ja = j0 + 2*jj, jb = ja + 1;
            float va = fmaf(x0, sW1[ja*3], fmaf(x1, sW1[ja*3+1], fmaf(x2, sW1[ja*3+2], sB1[ja])));
            float vb = fmaf(x0, sW1[jb*3], fmaf(x1, sW1[jb*3+1], fmaf(x2, sW1[jb*3+2], sB1[jb])));
            __half2 hv = __floats2half2_rn(gelu_exact(va), gelu_exact(vb));
            pw[jj] = *reinterpret_cast<uint32_t*>(&hv);
        }
        *(uint4*)(smem + 49152 + st*4096 + r*64 + ((c ^ ((r>>1)&3)) << 4)) = pk;
        #pragma unroll
        for (int it = 0; it < 4; it++){
            const int idx = it*256 + t, rr = idx >> 2, cc = idx & 3;
            uint32_t db = sb + st*16384 + rr*64 + (uint32_t)((cc ^ ((rr>>1)&3)) << 4);
            CP16(db, (const void*)(W2 + (size_t)rr*256 + kc*32 + cc*8));
        }
        CP_COMMIT();
    };

    produce1(0, 0); produce1(1, 1);

    int ccur = 0, pcur = 2;
    #pragma unroll 1
    for (int kc = 0; kc < 8; kc++){
        CP_WAIT1();
        __syncthreads();
        const uint32_t aB = sb + 49152u + ccur*4096;
        const uint32_t bB = sb + ccur*16384;
        #pragma unroll
        for (int s = 0; s < 2; s++){
            const uint32_t sx = (uint32_t)s << 5;
            uint32_t afr[2][4], bfr[8][2];
            #pragma unroll
            for (int mi = 0; mi < 2; mi++)
                ldsm4(afr[mi][0], afr[mi][1], afr[mi][2], afr[mi][3],
                      aB + (offA[mi] ^ sx));
            #pragma unroll
            for (int p = 0; p < 4; p++)
                ldsm4(bfr[2*p][0], bfr[2*p][1], bfr[2*p+1][0], bfr[2*p+1][1],
                      bB + (offB[p] ^ sx));
            #pragma unroll
            for (int mi = 0; mi < 2; mi++)
                #pragma unroll
                for (int nj = 0; nj < 8; nj++)
                    mma16(acc[mi][nj], afr[mi], bfr[nj]);
        }
        if (kc + 2 < 8) produce1(kc + 2, pcur); else CP_COMMIT();
        ccur = (ccur == 2) ? 0 : ccur + 1;
        pcur = (pcur == 2) ? 0 : pcur + 1;
    }

    __syncthreads();

    auto produce2 = [&](int kc){
        const int st = kc & 1;
        #pragma unroll
        for (int it = 0; it < 4; it++){
            const int idx = it*256 + t, rr = idx >> 2, cc = idx & 3;
            uint32_t db = sb + 32768 + st*16384 + rr*64 + (uint32_t)((cc ^ ((rr>>1)&3)) << 4);
            CP16(db, (const void*)(W3 + (size_t)rr*256 + kc*32 + cc*8));
        }
        CP_COMMIT();
    };
    produce2(0);

    #pragma unroll
    for (int mi = 0; mi < 2; mi++){
        const int lr0 = wm*32 + mi*16 + gid;
        const int lr1 = lr0 + 8;
        #pragma unroll
        for (int nj = 0; nj < 8; nj++){
            const int cb = wn*64 + nj*8 + 2*tig;
            const float b0 = b2[cb], b1 = b2[cb+1];
            __half2 lo = __floats2half2_rn(gelu_exact(acc[mi][nj][0] + b0),
                                           gelu_exact(acc[mi][nj][1] + b1));
            __half2 hi = __floats2half2_rn(gelu_exact(acc[mi][nj][2] + b0),
                                           gelu_exact(acc[mi][nj][3] + b1));
            const int blk = cb >> 3;
            *(__half2*)(smem + lr0*512 + ((blk ^ (lr0 & 7)) << 4) + 4*tig) = lo;
            *(__half2*)(smem + lr1*512 + ((blk ^ (lr1 & 7)) << 4) + 4*tig) = hi;
            acc[mi][nj][0] = 0.f; acc[mi][nj][1] = 0.f;
            acc[mi][nj][2] = 0.f; acc[mi][nj][3] = 0.f;
        }
    }

    #pragma unroll 1
    for (int kc = 0; kc < 8; kc++){
        __syncthreads();
        if (kc + 1 < 8) produce2(kc + 1); else CP_COMMIT();
        CP_WAIT1();
        __syncthreads();
        const uint32_t bB = sb + 32768u + (kc & 1)*16384;
        #pragma unroll
        for (int s = 0; s < 2; s++){
            const uint32_t sx = (uint32_t)s << 5;
            uint32_t afr[2][4], bfr[8][2];
            #pragma unroll
            for (int mi = 0; mi < 2; mi++){
                const int blk = kc*4 + h4;
                const uint32_t offM = (uint32_t)((blk ^ swM[mi]) << 4);
                ldsm4(afr[mi][0], afr[mi][1], afr[mi][2], afr[mi][3],
                      sb + baseM[mi] + (offM ^ sx));
            }
            #pragma unroll
            for (int p = 0; p < 4; p++)
                ldsm4(bfr[2*p][0], bfr[2*p][1], bfr[2*p+1][0], bfr[2*p+1][1],
                      bB + (offB[p] ^ sx));
            #pragma unroll
            for (int mi = 0; mi < 2; mi++)
                #pragma unroll
                for (int nj = 0; nj < 8; nj++)
                    mma16(acc[mi][nj], afr[mi], bfr[nj]);
        }
    }

    #pragma unroll
    for (int mi = 0; mi < 2; mi++){
        const int r0 = m0 + wm*32 + mi*16 + gid;
        const int r1 = r0 + 8;
        const float p00 = pos[(size_t)r0*2], p01 = pos[(size_t)r0*2 + 1];
        const float p10 = pos[(size_t)r1*2], p11 = pos[(size_t)r1*2 + 1];
        #pragma unroll
        for (int nj = 0; nj < 8; nj++){
            const int cb = wn*64 + nj*8 + 2*tig;
            const float b0 = b3[cb], b1 = b3[cb+1];
            float v0 = acc[mi][nj][0] + b0, v1 = acc[mi][nj][1] + b1;
            float v2 = acc[mi][nj][2] + b0, v3 = acc[mi][nj][3] + b1;
            const int o0 = cb, o1 = cb + 1;
            const float ba0 = bfour[(o0 & 127)*2], bb0 = bfour[(o0 & 127)*2 + 1];
            const float ba1 = bfour[(o1 & 127)*2], bb1 = bfour[(o1 & 127)*2 + 1];
            const float TP = 6.283185307179586f;
            float pl0 = TP*(p00*ba0 + p01*bb0), pl1 = TP*(p00*ba1 + p01*bb1);
            float ph0 = TP*(p10*ba0 + p11*bb0), ph1 = TP*(p10*ba1 + p11*bb1);
            v0 += (o0 < 128) ? __cosf(pl0) : __sinf(pl0);
            v1 += (o1 < 128) ? __cosf(pl1) : __sinf(pl1);
            v2 += (o0 < 128) ? __cosf(ph0) : __sinf(ph0);
            v3 += (o1 < 128) ? __cosf(ph1) : __sinf(ph1);
            *(__half2*)(hh + (size_t)r0*256 + cb) = __floats2half2_rn(v0, v1);
            *(__half2*)(hh + (size_t)r1*256 + cb) = __floats2half2_rn(v2, v3);
        }
    }
}

// ---------------------------------------------------------------------------
// Edge kernel: 128 edges (= 8 dsts) per block, 512 threads = 16 warps (4mx4n),
// warp tile 32x64, 3-stage pipeline, 1 CTA/SM (RF-full).
//   m2 = gelu([gelu(ea[src]+eb[dst])] @ W2^T + b2)   (K=512)
//   m2mean[dst] = mean_16(m2)  -> gmem fp16          (W3 hoisted out: linear)
// SMEM 72KB: W2 3x16KB [0,48K), A 3x8KB [48K,72K). eb read from gmem (L2).
// ---------------------------------------------------------------------------
#define EDGE_SMEM (72*1024)

__global__ __launch_bounds__(512, 1)
void edge_fused(const __half* __restrict__ eaH, const float* __restrict__ ebF,
                const __half* __restrict__ W2, const float* __restrict__ b2,
                __half* __restrict__ m2mean, const int* __restrict__ me32)
{
    extern __shared__ char smem[];
    __shared__ int sSrc[128], sDst[128];
    const int t    = threadIdx.x;
    const int lane = t & 31;
    const int w    = t >> 5;
    const int wm   = w >> 2, wn = w & 3;          // 4 x 4 warp grid
    const int tig  = lane & 3;
    const int m0   = blockIdx.x * 128;
    const uint32_t sb = smem_u32(smem);

    if (t < 128){
        const int e = m0 + t; int s, d;
        if (g_is64){ d = me32[4*e]; s = me32[4*e+2]; }
        else       { d = me32[2*e]; s = me32[2*e+1]; }
        sSrc[t] = s; sDst[t] = d;
    }
    __syncthreads();

    // per-lane ldmatrix offsets
    uint32_t offA[2], offB[4];
    const int l8 = lane & 7;
    const int h3 = (lane >> 3) & 1;
    const int h4 = lane >> 4;
    #pragma unroll
    for (int mi = 0; mi < 2; mi++){
        int rA = wm*32 + mi*16 + h3*8 + l8;          // 0..127
        int sw = (rA >> 1) & 3;
        offA[mi] = (uint32_t)(rA*64) + (uint32_t)((h4 ^ sw) << 4);
    }
    #pragma unroll
    for (int p = 0; p < 4; p++){
        int rB = wn*64 + p*16 + h4*8 + l8;           // 0..255
        int sw = (rB >> 1) & 3;
        offB[p] = (uint32_t)(rB*64) + (uint32_t)((h3 ^ sw) << 4);
    }

    float acc[2][8][4];
    #pragma unroll
    for (int i = 0; i < 2; i++)
        #pragma unroll
        for (int j = 0; j < 8; j++)
            #pragma unroll
            for (int r = 0; r < 4; r++) acc[i][j][r] = 0.f;

    // ---- producer: A = gelu(ea[src]+eb[dst]) (STS), B = W2 (cp.async)
    // A tile 128x32 fp16 = 512 uint4 -> 1 per thread; W2 tile 256x32 = 2/thread.
    auto produce1 = [&](int kc, int st){
        const int r = t >> 2, c = t & 3;             // r: 0..127
        const int k0 = kc*32 + c*8;
        uint4 av = *(const uint4*)(eaH + (size_t)sSrc[r]*512 + k0);
        const float* pb = ebF + (size_t)sDst[r]*512 + k0;
        float4 e0 = *(const float4*)pb, e1 = *(const float4*)(pb + 4);
        const __half2* ah = (const __half2*)&av;
        float2 f0 = __half22float2(ah[0]), f1 = __half22float2(ah[1]);
        float2 f2 = __half22float2(ah[2]), f3 = __half22float2(ah[3]);
        __half2 h0 = __floats2half2_rn(gelu_exact(f0.x+e0.x), gelu_exact(f0.y+e0.y));
        __half2 h1 = __floats2half2_rn(gelu_exact(f1.x+e0.z), gelu_exact(f1.y+e0.w));
        __half2 h2 = __floats2half2_rn(gelu_exact(f2.x+e1.x), gelu_exact(f2.y+e1.y));
        __half2 h3v = __floats2half2_rn(gelu_exact(f3.x+e1.z), gelu_exact(f3.y+e1.w));
        uint4 pk;
        pk.x = *reinterpret_cast<uint32_t*>(&h0);
        pk.y = *reinterpret_cast<uint32_t*>(&h1);
        pk.z = *reinterpret_cast<uint32_t*>(&h2);
        pk.w = *reinterpret_cast<uint32_t*>(&h3v);
        *(uint4*)(smem + 49152 + st*8192 + r*64 + ((c ^ ((r>>1)&3)) << 4)) = pk;
        #pragma unroll
        for (int it = 0; it < 2; it++){
            const int idx = it*512 + t, rr = idx >> 2, cc = idx & 3;
            uint32_t db = sb + st*16384 + rr*64 + (uint32_t)((cc ^ ((rr>>1)&3)) << 4);
            CP16(db, (const void*)(W2 + (size_t)rr*512 + kc*32 + cc*8));
        }
        CP_COMMIT();
    };

    produce1(0, 0); produce1(1, 1);

    int ccur = 0, pcur = 2;
    #pragma unroll 1
    for (int kc = 0; kc < 16; kc++){
        CP_WAIT1();
        __syncthreads();
        const uint32_t aB = sb + 49152u + ccur*8192;
        const uint32_t bB = sb + ccur*16384;
        #pragma unroll
        for (int s = 0; s < 2; s++){
            const uint32_t sx = (uint32_t)s << 5;
            uint32_t afr[2][4], bfr[8][2];
            #pragma unroll
            for (int mi = 0; mi < 2; mi++)
                ldsm4(afr[mi][0], afr[mi][1], afr[mi][2], afr[mi][3],
                      aB + (offA[mi] ^ sx));
            #pragma unroll
            for (int p = 0; p < 4; p++)
                ldsm4(bfr[2*p][0], bfr[2*p][1], bfr[2*p+1][0], bfr[2*p+1][1],
                      bB + (offB[p] ^ sx));
            #pragma unroll
            for (int mi = 0; mi < 2; mi++)
                #pragma unroll
                for (int nj = 0; nj < 8; nj++)
                    mma16(acc[mi][nj], afr[mi], bfr[nj]);
        }
        if (kc + 2 < 16) produce1(kc + 2, pcur); else CP_COMMIT();
        ccur = (ccur == 2) ? 0 : ccur + 1;
        pcur = (pcur == 2) ? 0 : pcur + 1;
    }

    // ---- epilogue: m2mean[dst] = mean_16( gelu(acc + b2) )
    // mi tile = 16 consecutive edges = exactly one dst (wm*2 + mi of 8).
    #pragma unroll
    for (int mi = 0; mi < 2; mi++){
        #pragma unroll
        for (int nj = 0; nj < 8; nj++){
            const int cb = wn*64 + nj*8 + 2*tig;
            const float b0 = b2[cb], b1 = b2[cb+1];
            float s0 = gelu_exact(acc[mi][nj][0] + b0) + gelu_exact(acc[mi][nj][2] + b0);
            float s1 = gelu_exact(acc[mi][nj][1] + b1) + gelu_exact(acc[mi][nj][3] + b1);
            s0 += __shfl_xor_sync(0xffffffffu, s0, 4);
            s0 += __shfl_xor_sync(0xffffffffu, s0, 8);
            s0 += __shfl_xor_sync(0xffffffffu, s0, 16);
            s1 += __shfl_xor_sync(0xffffffffu, s1, 4);
            s1 += __shfl_xor_sync(0xffffffffu, s1, 8);
            s1 += __shfl_xor_sync(0xffffffffu, s1, 16);
            if (lane < 4){
                const int dst = (m0 >> 4) + wm*2 + mi;
                *(__half2*)(m2mean + (size_t)dst*256 + cb) =
                    __floats2half2_rn(s0 * 0.0625f, s1 * 0.0625f);
            }
        }
    }
}

// ---------------------------------------------------------------------------
extern "C" void kernel_launch(void* const* d_in, const int* in_sizes, int n_in,
                              void* d_out, int out_size)
{
    const float* x        = (const float*)d_in[0];
    const float* mesh_pos = (const float*)d_in[1];
    const int*   me32     = (const int*)  d_in[2];
    const float* ip_w1 = (const float*)d_in[4];
    const float* ip_b1 = (const float*)d_in[5];
    const float* ip_w2 = (const float*)d_in[6];
    const float* ip_b2 = (const float*)d_in[7];
    const float* ip_w3 = (const float*)d_in[8];
    const float* ip_b3 = (const float*)d_in[9];
    const float* bf    = (const float*)d_in[10];
    const float* mw1   = (const float*)d_in[11];
    const float* mb1   = (const float*)d_in[12];
    const float* mw2   = (const float*)d_in[13];
    const float* mb2   = (const float*)d_in[14];
    const float* mw3   = (const float*)d_in[15];
    const float* mb3   = (const float*)d_in[16];
    float* out = (float*)d_out;

    __half *m2mp, *hhp, *eaHp, *w2h, *w3h, *mw1h, *mw2h, *mw3h;
    float  *ebp;
    cudaGetSymbolAddress((void**)&m2mp, g_m2m);
    cudaGetSymbolAddress((void**)&hhp,  g_hh);
    cudaGetSymbolAddress((void**)&eaHp, g_eaH);
    cudaGetSymbolAddress((void**)&ebp,  g_eb);
    cudaGetSymbolAddress((void**)&w2h,  g_w2h);
    cudaGetSymbolAddress((void**)&w3h,  g_w3h);
    cudaGetSymbolAddress((void**)&mw1h, g_mw1h);
    cudaGetSymbolAddress((void**)&mw2h, g_mw2h);
    cudaGetSymbolAddress((void**)&mw3h, g_mw3h);

    cudaFuncSetAttribute(gemm16<256,4,false>, cudaFuncAttributeMaxDynamicSharedMemorySize, GEMM_SMEM);
    cudaFuncSetAttribute(gemm16<256,0,true >, cudaFuncAttributeMaxDynamicSharedMemorySize, GEMM_SMEM);
    cudaFuncSetAttribute(node_fused,          cudaFuncAttributeMaxDynamicSharedMemorySize, FUSED_SMEM);
    cudaFuncSetAttribute(edge_fused,          cudaFuncAttributeMaxDynamicSharedMemorySize, EDGE_SMEM);

    // single fp16 weight prep launch (also detects mesh_edges dtype)
    f2h_all<<<576, 256>>>(ip_w2, ip_w3, mw1, mw2, mw3,
                          w2h, w3h, mw1h, mw2h, mw3h, me32);

    // node encoder fully fused: h1 (in-producer) + layers 2,3 (+fourier) -> hh
    node_fused<<<N_NODES/64, 256, FUSED_SMEM>>>(
        x, ip_w1, ip_b1, w2h, ip_b2, w3h, ip_b3, mesh_pos, bf, hhp);

    // hoisted edge layer-1 halves: ea fp16 (no bias), eb fp32 (+b1)
    gemm16<256,4,false><<<dim3(N_NODES/128,4), 256, GEMM_SMEM>>>(
        hhp, 256, mw1h, 512, nullptr, eaHp, 512);
    gemm16<256,0,true ><<<dim3(N_DST/128,4), 256, GEMM_SMEM>>>(
        hhp, 256, mw1h + 256, 512, mb1, ebp, 512);

    // edge layer 2 + segment mean (W3 hoisted past the mean), 128 edges/block
    edge_fused<<<N_EDGES/128, 512, EDGE_SMEM>>>(
        eaHp, ebp, mw2h, mb2, m2mp, me32);

    // final: out = m2mean @ W3^T + b3   (16384 x 256, K=256)
    gemm16<256,0,true ><<<dim3(N_DST/128,2), 256, GEMM_SMEM>>>(
        m2mp, 256, mw3h, 256, mb3, out, 256);
}

// round 15
// speedup vs baseline: 1.0563x; 1.0563x over previous
#include <cuda_runtime.h>
#include <cuda_fp16.h>
#include <math.h>
#include <stdint.h>

#define N_NODES 131072
#define N_DST   16384
#define DEG     16
#define N_EDGES (N_DST*DEG)
#define HID     256

// ---------------- global scratch (device globals: no runtime alloc) --------
__device__ __align__(16) __half g_m2m[(size_t)N_DST * 256];     // m2mean
__device__ __align__(16) __half g_hh [(size_t)N_NODES * 256];
__device__ __align__(16) __half g_eaH[(size_t)N_NODES * 512];
__device__ __align__(16) float  g_eb [(size_t)N_DST   * 512];
__device__ __align__(16) __half g_w2h [256*256];
__device__ __align__(16) __half g_w3h [256*256];
__device__ __align__(16) __half g_mw1h[512*512];
__device__ __align__(16) __half g_mw2h[256*512];
__device__ __align__(16) __half g_mw3h[256*256];
__device__ int g_is64;

__device__ __forceinline__ float gelu_exact(float x){
    return 0.5f * x * (1.0f + erff(x * 0.70710678118654752f));
}
__device__ __forceinline__ uint32_t smem_u32(const void* p){
    uint32_t a;
    asm("{ .reg .u64 t; cvta.to.shared.u64 t, %1; cvt.u32.u64 %0, t; }" : "=r"(a) : "l"(p));
    return a;
}
__device__ __forceinline__ void mma16(float* c, const uint32_t* a, const uint32_t* b){
    asm volatile("mma.sync.aligned.m16n8k16.row.col.f32.f16.f16.f32 "
        "{%0,%1,%2,%3}, {%4,%5,%6,%7}, {%8,%9}, {%0,%1,%2,%3};"
        : "+f"(c[0]), "+f"(c[1]), "+f"(c[2]), "+f"(c[3])
        : "r"(a[0]), "r"(a[1]), "r"(a[2]), "r"(a[3]), "r"(b[0]), "r"(b[1]));
}
__device__ __forceinline__ void ldsm4(uint32_t& r0, uint32_t& r1, uint32_t& r2, uint32_t& r3,
                                      uint32_t addr){
    asm volatile("ldmatrix.sync.aligned.m8n8.x4.shared.b16 {%0,%1,%2,%3}, [%4];"
        : "=r"(r0), "=r"(r1), "=r"(r2), "=r"(r3) : "r"(addr));
}
#define CP16(dst, src) \
    asm volatile("cp.async.ca.shared.global [%0], [%1], 16;" :: "r"(dst), "l"(src) : "memory")
#define CP_COMMIT() asm volatile("cp.async.commit_group;" ::: "memory")
#define CP_WAIT2()  asm volatile("cp.async.wait_group 2;"  ::: "memory")
#define CP_WAIT1()  asm volatile("cp.async.wait_group 1;"  ::: "memory")

// ---------------------------------------------------------------------------
// one-shot fp16 conversion of all five weight matrices + edge-dtype detect
__global__ __launch_bounds__(256)
void f2h_all(const float* __restrict__ w2, const float* __restrict__ w3,
             const float* __restrict__ m1, const float* __restrict__ m2,
             const float* __restrict__ m3,
             __half* __restrict__ dw2, __half* __restrict__ dw3,
             __half* __restrict__ dm1, __half* __restrict__ dm2,
             __half* __restrict__ dm3, const int* __restrict__ me32)
{
    int i = blockIdx.x*256 + threadIdx.x;          // float4 index, total 147456
    if (i == 0) g_is64 = (me32[32] != 1) ? 1 : 0;
    const float* s; __half* d; int off;
    if      (i <  16384){ s = w2; d = dw2; off = i; }
    else if (i <  32768){ s = w3; d = dw3; off = i - 16384; }
    else if (i <  98304){ s = m1; d = dm1; off = i - 32768; }
    else if (i < 131072){ s = m2; d = dm2; off = i - 98304; }
    else                { s = m3; d = dm3; off = i - 131072; }
    float4 v = ((const float4*)s)[off];
    __half2 h0 = __floats2half2_rn(v.x, v.y), h1 = __floats2half2_rn(v.z, v.w);
    uint2 pk;
    pk.x = *reinterpret_cast<uint32_t*>(&h0);
    pk.y = *reinterpret_cast<uint32_t*>(&h1);
    ((uint2*)d)[off] = pk;
}

// ---------------------------------------------------------------------------
// fp16 mma.sync GEMM (R11 proven): block 128x128, BK=32, 8 warps (4m x 2n),
// warp tile 32x64, 4-stage cp.async, 64KB smem, 2 CTAs/SM.
// EPI: 0=fp32 store(+bias), 4=plain fp16.
// ---------------------------------------------------------------------------
#define GEMM_SMEM (64*1024)

template<int K, int EPI, bool HAS_BIAS>
__global__ __launch_bounds__(256, 2)
void gemm16(const __half* __restrict__ A, int lda,
            const __half* __restrict__ W, int ldw,
            const float* __restrict__ bias,
            void* __restrict__ Cout, int ldc)
{
    extern __shared__ char smem[];
    const int t    = threadIdx.x;
    const int lane = t & 31;
    const int w    = t >> 5;
    const int wm   = w >> 1, wn = w & 1;
    const int gid  = lane >> 2, tig = lane & 3;
    const int m0   = blockIdx.x * 128;
    const int n0   = blockIdx.y * 128;
    const uint32_t sb = smem_u32(smem);

    uint32_t offA[2], offB[4];
    {
        const int l8 = lane & 7;
        const int h3 = (lane >> 3) & 1;
        const int h4 = lane >> 4;
        #pragma unroll
        for (int mi = 0; mi < 2; mi++){
            int rA = wm*32 + mi*16 + h3*8 + l8;
            int sw = (rA >> 1) & 3;
            offA[mi] = (uint32_t)(rA*64) + (uint32_t)((h4 ^ sw) << 4);
        }
        #pragma unroll
        for (int p = 0; p < 4; p++){
            int rB = wn*64 + p*16 + h4*8 + l8;
            int sw = (rB >> 1) & 3;
            offB[p] = (uint32_t)(rB*64) + (uint32_t)((h3 ^ sw) << 4);
        }
    }

    float acc[2][8][4];
    #pragma unroll
    for (int i = 0; i < 2; i++)
        #pragma unroll
        for (int j = 0; j < 8; j++)
            #pragma unroll
            for (int r = 0; r < 4; r++) acc[i][j][r] = 0.f;

    constexpr int NC = K / 32;

    auto produce = [&](int kc){
        const int st = kc & 3;
        #pragma unroll
        for (int it = 0; it < 2; it++){
            const int idx = it*256 + t, r = idx >> 2, c = idx & 3;
            uint32_t dst = sb + st*8192 + r*64 + (uint32_t)((c ^ ((r>>1)&3)) << 4);
            CP16(dst, (const void*)(A + (size_t)(m0 + r)*lda + kc*32 + c*8));
        }
        #pragma unroll
        for (int it = 0; it < 2; it++){
            const int idx = it*256 + t, rr = idx >> 2, cc = idx & 3;
            uint32_t db = sb + 32768 + st*8192 + rr*64 + (uint32_t)((cc ^ ((rr>>1)&3)) << 4);
            CP16(db, (const void*)(W + (size_t)(n0 + rr)*ldw + kc*32 + cc*8));
        }
        CP_COMMIT();
    };

    produce(0); produce(1); produce(2);

    #pragma unroll 1
    for (int kc = 0; kc < NC; kc++){
        CP_WAIT2();
        __syncthreads();
        const uint32_t aB = sb + (kc & 3)*8192;
        const uint32_t bB = sb + 32768u + (kc & 3)*8192;
        #pragma unroll
        for (int s = 0; s < 2; s++){
            const uint32_t sx = (uint32_t)s << 5;
            uint32_t afr[2][4], bfr[8][2];
            #pragma unroll
            for (int mi = 0; mi < 2; mi++)
                ldsm4(afr[mi][0], afr[mi][1], afr[mi][2], afr[mi][3],
                      aB + (offA[mi] ^ sx));
            #pragma unroll
            for (int p = 0; p < 4; p++)
                ldsm4(bfr[2*p][0], bfr[2*p][1], bfr[2*p+1][0], bfr[2*p+1][1],
                      bB + (offB[p] ^ sx));
            #pragma unroll
            for (int mi = 0; mi < 2; mi++)
                #pragma unroll
                for (int nj = 0; nj < 8; nj++)
                    mma16(acc[mi][nj], afr[mi], bfr[nj]);
        }
        if (kc + 3 < NC) produce(kc + 3); else CP_COMMIT();
    }

    #pragma unroll
    for (int mi = 0; mi < 2; mi++){
        const int r0 = m0 + wm*32 + mi*16 + gid;
        const int r1 = r0 + 8;
        #pragma unroll
        for (int nj = 0; nj < 8; nj++){
            const int cb = n0 + wn*64 + nj*8 + 2*tig;
            float v0 = acc[mi][nj][0], v1 = acc[mi][nj][1];
            float v2 = acc[mi][nj][2], v3 = acc[mi][nj][3];
            if (HAS_BIAS){
                const float b0 = bias[cb], b1 = bias[cb+1];
                v0 += b0; v1 += b1; v2 += b0; v3 += b1;
            }
            if (EPI == 0){
                float* C = (float*)Cout;
                *(float2*)(C + (size_t)r0*ldc + cb) = make_float2(v0, v1);
                *(float2*)(C + (size_t)r1*ldc + cb) = make_float2(v2, v3);
            } else {
                __half* C = (__half*)Cout;
                *(__half2*)(C + (size_t)r0*ldc + cb) = __floats2half2_rn(v0, v1);
                *(__half2*)(C + (size_t)r1*ldc + cb) = __floats2half2_rn(v2, v3);
            }
        }
    }
}

// ---------------------------------------------------------------------------
// Dual GEMM: ea (4096 blocks) + eb (512 blocks) in ONE launch, K=256.
// Block i < 4096:  ea tile: A=hh[m], W=W1[:, :256], C=eaH fp16 (no bias)
// Block i >= 4096: eb tile: A=hh[m<16384], W=W1[:, 256:], C=eb fp32 (+b1)
// Same engine as gemm16 (4-stage, 2 CTAs/SM); branch is block-uniform.
// ---------------------------------------------------------------------------
__global__ __launch_bounds__(256, 2)
void gemm16_dual(const __half* __restrict__ hh,
                 const __half* __restrict__ W1, const float* __restrict__ b1,
                 __half* __restrict__ eaH, float* __restrict__ ebF)
{
    extern __shared__ char smem[];
    const int t    = threadIdx.x;
    const int lane = t & 31;
    const int w    = t >> 5;
    const int wm   = w >> 1, wn = w & 1;
    const int gid  = lane >> 2, tig = lane & 3;
    const uint32_t sb = smem_u32(smem);

    const bool is_eb = (blockIdx.x >= 4096);
    const int  bi    = is_eb ? (int)blockIdx.x - 4096 : (int)blockIdx.x;
    const int  m0    = (bi >> 2) * 128;
    const int  n0    = (bi & 3) * 128;
    const __half* A  = hh;                          // lda = 256
    const __half* W  = is_eb ? (W1 + 256) : W1;     // ldw = 512

    uint32_t offA[2], offB[4];
    {
        const int l8 = lane & 7;
        const int h3 = (lane >> 3) & 1;
        const int h4 = lane >> 4;
        #pragma unroll
        for (int mi = 0; mi < 2; mi++){
            int rA = wm*32 + mi*16 + h3*8 + l8;
            int sw = (rA >> 1) & 3;
            offA[mi] = (uint32_t)(rA*64) + (uint32_t)((h4 ^ sw) << 4);
        }
        #pragma unroll
        for (int p = 0; p < 4; p++){
            int rB = wn*64 + p*16 + h4*8 + l8;
            int sw = (rB >> 1) & 3;
            offB[p] = (uint32_t)(rB*64) + (uint32_t)((h3 ^ sw) << 4);
        }
    }

    float acc[2][8][4];
    #pragma unroll
    for (int i = 0; i < 2; i++)
        #pragma unroll
        for (int j = 0; j < 8; j++)
            #pragma unroll
            for (int r = 0; r < 4; r++) acc[i][j][r] = 0.f;

    auto produce = [&](int kc){
        const int st = kc & 3;
        #pragma unroll
        for (int it = 0; it < 2; it++){
            const int idx = it*256 + t, r = idx >> 2, c = idx & 3;
            uint32_t dst = sb + st*8192 + r*64 + (uint32_t)((c ^ ((r>>1)&3)) << 4);
            CP16(dst, (const void*)(A + (size_t)(m0 + r)*256 + kc*32 + c*8));
        }
        #pragma unroll
        for (int it = 0; it < 2; it++){
            const int idx = it*256 + t, rr = idx >> 2, cc = idx & 3;
            uint32_t db = sb + 32768 + st*8192 + rr*64 + (uint32_t)((cc ^ ((rr>>1)&3)) << 4);
            CP16(db, (const void*)(W + (size_t)(n0 + rr)*512 + kc*32 + cc*8));
        }
        CP_COMMIT();
    };

    produce(0); produce(1); produce(2);

    #pragma unroll 1
    for (int kc = 0; kc < 8; kc++){
        CP_WAIT2();
        __syncthreads();
        const uint32_t aB = sb + (kc & 3)*8192;
        const uint32_t bB = sb + 32768u + (kc & 3)*8192;
        #pragma unroll
        for (int s = 0; s < 2; s++){
            const uint32_t sx = (uint32_t)s << 5;
            uint32_t afr[2][4], bfr[8][2];
            #pragma unroll
            for (int mi = 0; mi < 2; mi++)
                ldsm4(afr[mi][0], afr[mi][1], afr[mi][2], afr[mi][3],
                      aB + (offA[mi] ^ sx));
            #pragma unroll
            for (int p = 0; p < 4; p++)
                ldsm4(bfr[2*p][0], bfr[2*p][1], bfr[2*p+1][0], bfr[2*p+1][1],
                      bB + (offB[p] ^ sx));
            #pragma unroll
            for (int mi = 0; mi < 2; mi++)
                #pragma unroll
                for (int nj = 0; nj < 8; nj++)
                    mma16(acc[mi][nj], afr[mi], bfr[nj]);
        }
        if (kc + 3 < 8) produce(kc + 3); else CP_COMMIT();
    }

    #pragma unroll
    for (int mi = 0; mi < 2; mi++){
        const int r0 = m0 + wm*32 + mi*16 + gid;
        const int r1 = r0 + 8;
        #pragma unroll
        for (int nj = 0; nj < 8; nj++){
            const int cb = n0 + wn*64 + nj*8 + 2*tig;
            float v0 = acc[mi][nj][0], v1 = acc[mi][nj][1];
            float v2 = acc[mi][nj][2], v3 = acc[mi][nj][3];
            if (is_eb){
                const float b0 = b1[cb], b1v = b1[cb+1];
                v0 += b0; v1 += b1v; v2 += b0; v3 += b1v;
                *(float2*)(ebF + (size_t)r0*512 + cb) = make_float2(v0, v1);
                *(float2*)(ebF + (size_t)r1*512 + cb) = make_float2(v2, v3);
            } else {
                *(__half2*)(eaH + (size_t)r0*512 + cb) = __floats2half2_rn(v0, v1);
                *(__half2*)(eaH + (size_t)r1*512 + cb) = __floats2half2_rn(v2, v3);
            }
        }
    }
}

// ---------------------------------------------------------------------------
// Fused node-encoder kernel (R11 proven), 2 CTAs/SM, 64 nodes/block.
// ---------------------------------------------------------------------------
#define FUSED_SMEM (64*1024)

__global__ __launch_bounds__(256, 2)
void node_fused(const float* __restrict__ xg,
                const float* __restrict__ w1g, const float* __restrict__ b1g,
                const __half* __restrict__ W2, const float* __restrict__ b2,
                const __half* __restrict__ W3, const float* __restrict__ b3,
                const float* __restrict__ pos, const float* __restrict__ bfour,
                __half* __restrict__ hh)
{
    extern __shared__ char smem[];
    __shared__ float sX[64*3];
    __shared__ float sW1[256*3];
    __shared__ float sB1[256];
    const int t    = threadIdx.x;
    const int lane = t & 31;
    const int w    = t >> 5;
    const int wm   = w >> 2, wn = w & 3;
    const int gid  = lane >> 2, tig = lane & 3;
    const int m0   = blockIdx.x * 64;
    const uint32_t sb = smem_u32(smem);

    if (t < 192) sX[t] = xg[(size_t)m0*3 + t];
    for (int i = t; i < 768; i += 256) sW1[i] = w1g[i];
    sB1[t] = b1g[t];
    __syncthreads();

    uint32_t offA[2], offB[4], baseM[2];
    int swM[2];
    const int l8 = lane & 7;
    const int h3 = (lane >> 3) & 1;
    const int h4 = lane >> 4;
    #pragma unroll
    for (int mi = 0; mi < 2; mi++){
        int rA = wm*32 + mi*16 + h3*8 + l8;
        int sw = (rA >> 1) & 3;
        offA[mi] = (uint32_t)(rA*64) + (uint32_t)((h4 ^ sw) << 4);
        baseM[mi] = (uint32_t)(rA*512);
        swM[mi] = rA & 7;
    }
    #pragma unroll
    for (int p = 0; p < 4; p++){
        int rB = wn*64 + p*16 + h4*8 + l8;
        int sw = (rB >> 1) & 3;
        offB[p] = (uint32_t)(rB*64) + (uint32_t)((h3 ^ sw) << 4);
    }

    float acc[2][8][4];
    #pragma unroll
    for (int i = 0; i < 2; i++)
        #pragma unroll
        for (int j = 0; j < 8; j++)
            #pragma unroll
            for (int r = 0; r < 4; r++) acc[i][j][r] = 0.f;

    auto produce1 = [&](int kc, int st){
        const int r = t >> 2, c = t & 3;
        const int j0 = kc*32 + c*8;
        const float x0 = sX[r*3], x1 = sX[r*3+1], x2 = sX[r*3+2];
        uint4 pk;
        uint32_t* pw = (uint32_t*)&pk;
        #pragma unroll
        for (int jj = 0; jj < 4; jj++){
            const int ja = j0 + 2*jj, jb = ja + 1;
            float va = fmaf(x0, sW1[ja*3], fmaf(x1, sW1[ja*3+1], fmaf(x2, sW1[ja*3+2], sB1[ja])));
            float vb = fmaf(x0, sW1[jb*3], fmaf(x1, sW1[jb*3+1], fmaf(x2, sW1[jb*3+2], sB1[jb])));
            __half2 hv = __floats2half2_rn(gelu_exact(va), gelu_exact(vb));
            pw[jj] = *reinterpret_cast<uint32_t*>(&hv);
        }
        *(uint4*)(smem + 49152 + st*4096 + r*64 + ((c ^ ((r>>1)&3)) << 4)) = pk;
        #pragma unroll
        for (int it = 0; it < 4; it++){
            const int idx = it*256 + t, rr = idx >> 2, cc = idx & 3;
            uint32_t db = sb + st*16384 + rr*64 + (uint32_t)((cc ^ ((rr>>1)&3)) << 4);
            CP16(db, (const void*)(W2 + (size_t)rr*256 + kc*32 + cc*8));
        }
        CP_COMMIT();
    };

    produce1(0, 0); produce1(1, 1);

    int ccur = 0, pcur = 2;
    #pragma unroll 1
    for (int kc = 0; kc < 8; kc++){
        CP_WAIT1();
        __syncthreads();
        const uint32_t aB = sb + 49152u + ccur*4096;
        const uint32_t bB = sb + ccur*16384;
        #pragma unroll
        for (int s = 0; s < 2; s++){
            const uint32_t sx = (uint32_t)s << 5;
            uint32_t afr[2][4], bfr[8][2];
            #pragma unroll
            for (int mi = 0; mi < 2; mi++)
                ldsm4(afr[mi][0], afr[mi][1], afr[mi][2], afr[mi][3],
                      aB + (offA[mi] ^ sx));
            #pragma unroll
            for (int p = 0; p < 4; p++)
                ldsm4(bfr[2*p][0], bfr[2*p][1], bfr[2*p+1][0], bfr[2*p+1][1],
                      bB + (offB[p] ^ sx));
            #pragma unroll
            for (int mi = 0; mi < 2; mi++)
                #pragma unroll
                for (int nj = 0; nj < 8; nj++)
                    mma16(acc[mi][nj], afr[mi], bfr[nj]);
        }
        if (kc + 2 < 8) produce1(kc + 2, pcur); else CP_COMMIT();
        ccur = (ccur == 2) ? 0 : ccur + 1;
        pcur = (pcur == 2) ? 0 : pcur + 1;
    }

    __syncthreads();

    auto produce2 = [&](int kc){
        const int st = kc & 1;
        #pragma unroll
        for (int it = 0; it < 4; it++){
            const int idx = it*256 + t, rr = idx >> 2, cc = idx & 3;
            uint32_t db = sb + 32768 + st*16384 + rr*64 + (uint32_t)((cc ^ ((rr>>1)&3)) << 4);
            CP16(db, (const void*)(W3 + (size_t)rr*256 + kc*32 + cc*8));
        }
        CP_COMMIT();
    };
    produce2(0);

    #pragma unroll
    for (int mi = 0; mi < 2; mi++){
        const int lr0 = wm*32 + mi*16 + gid;
        const int lr1 = lr0 + 8;
        #pragma unroll
        for (int nj = 0; nj < 8; nj++){
            const int cb = wn*64 + nj*8 + 2*tig;
            const float b0 = b2[cb], b1 = b2[cb+1];
            __half2 lo = __floats2half2_rn(gelu_exact(acc[mi][nj][0] + b0),
                                           gelu_exact(acc[mi][nj][1] + b1));
            __half2 hi = __floats2half2_rn(gelu_exact(acc[mi][nj][2] + b0),
                                           gelu_exact(acc[mi][nj][3] + b1));
            const int blk = cb >> 3;
            *(__half2*)(smem + lr0*512 + ((blk ^ (lr0 & 7)) << 4) + 4*tig) = lo;
            *(__half2*)(smem + lr1*512 + ((blk ^ (lr1 & 7)) << 4) + 4*tig) = hi;
            acc[mi][nj][0] = 0.f; acc[mi][nj][1] = 0.f;
            acc[mi][nj][2] = 0.f; acc[mi][nj][3] = 0.f;
        }
    }

    #pragma unroll 1
    for (int kc = 0; kc < 8; kc++){
        __syncthreads();
        if (kc + 1 < 8) produce2(kc + 1); else CP_COMMIT();
        CP_WAIT1();
        __syncthreads();
        const uint32_t bB = sb + 32768u + (kc & 1)*16384;
        #pragma unroll
        for (int s = 0; s < 2; s++){
            const uint32_t sx = (uint32_t)s << 5;
            uint32_t afr[2][4], bfr[8][2];
            #pragma unroll
            for (int mi = 0; mi < 2; mi++){
                const int blk = kc*4 + h4;
                const uint32_t offM = (uint32_t)((blk ^ swM[mi]) << 4);
                ldsm4(afr[mi][0], afr[mi][1], afr[mi][2], afr[mi][3],
                      sb + baseM[mi] + (offM ^ sx));
            }
            #pragma unroll
            for (int p = 0; p < 4; p++)
                ldsm4(bfr[2*p][0], bfr[2*p][1], bfr[2*p+1][0], bfr[2*p+1][1],
                      bB + (offB[p] ^ sx));
            #pragma unroll
            for (int mi = 0; mi < 2; mi++)
                #pragma unroll
                for (int nj = 0; nj < 8; nj++)
                    mma16(acc[mi][nj], afr[mi], bfr[nj]);
        }
    }

    #pragma unroll
    for (int mi = 0; mi < 2; mi++){
        const int r0 = m0 + wm*32 + mi*16 + gid;
        const int r1 = r0 + 8;
        const float p00 = pos[(size_t)r0*2], p01 = pos[(size_t)r0*2 + 1];
        const float p10 = pos[(size_t)r1*2], p11 = pos[(size_t)r1*2 + 1];
        #pragma unroll
        for (int nj = 0; nj < 8; nj++){
            const int cb = wn*64 + nj*8 + 2*tig;
            const float b0 = b3[cb], b1 = b3[cb+1];
            float v0 = acc[mi][nj][0] + b0, v1 = acc[mi][nj][1] + b1;
            float v2 = acc[mi][nj][2] + b0, v3 = acc[mi][nj][3] + b1;
            const int o0 = cb, o1 = cb + 1;
            const float ba0 = bfour[(o0 & 127)*2], bb0 = bfour[(o0 & 127)*2 + 1];
            const float ba1 = bfour[(o1 & 127)*2], bb1 = bfour[(o1 & 127)*2 + 1];
            const float TP = 6.283185307179586f;
            float pl0 = TP*(p00*ba0 + p01*bb0), pl1 = TP*(p00*ba1 + p01*bb1);
            float ph0 = TP*(p10*ba0 + p11*bb0), ph1 = TP*(p10*ba1 + p11*bb1);
            v0 += (o0 < 128) ? __cosf(pl0) : __sinf(pl0);
            v1 += (o1 < 128) ? __cosf(pl1) : __sinf(pl1);
            v2 += (o0 < 128) ? __cosf(ph0) : __sinf(ph0);
            v3 += (o1 < 128) ? __cosf(ph1) : __sinf(ph1);
            *(__half2*)(hh + (size_t)r0*256 + cb) = __floats2half2_rn(v0, v1);
            *(__half2*)(hh + (size_t)r1*256 + cb) = __floats2half2_rn(v2, v3);
        }
    }
}

// ---------------------------------------------------------------------------
// Edge kernel (R10 proven): 64 edges (= 4 dsts) per block, 2 CTAs/SM:
//   m2 = gelu([gelu(ea[src]+eb[dst])] @ W2^T + b2)   (K=512)
//   m2mean[dst] = mean_16(m2)  -> gmem fp16
// SMEM 64KB: W2 3x16KB [0,48K), A 3x4KB [48K,60K). eb read from gmem (L2).
// ---------------------------------------------------------------------------
#define EDGE_SMEM (64*1024)

__global__ __launch_bounds__(256, 2)
void edge_fused(const __half* __restrict__ eaH, const float* __restrict__ ebF,
                const __half* __restrict__ W2, const float* __restrict__ b2,
                __half* __restrict__ m2mean, const int* __restrict__ me32)
{
    extern __shared__ char smem[];
    __shared__ int sSrc[64], sDst[64];
    const int t    = threadIdx.x;
    const int lane = t & 31;
    const int w    = t >> 5;
    const int wm   = w >> 2, wn = w & 3;
    const int tig  = lane & 3;
    const int m0   = blockIdx.x * 64;
    const uint32_t sb = smem_u32(smem);

    if (t < 64){
        const int e = m0 + t; int s, d;
        if (g_is64){ d = me32[4*e]; s = me32[4*e+2]; }
        else       { d = me32[2*e]; s = me32[2*e+1]; }
        sSrc[t] = s; sDst[t] = d;
    }
    __syncthreads();

    uint32_t offA[2], offB[4];
    const int l8 = lane & 7;
    const int h3 = (lane >> 3) & 1;
    const int h4 = lane >> 4;
    #pragma unroll
    for (int mi = 0; mi < 2; mi++){
        int rA = wm*32 + mi*16 + h3*8 + l8;
        int sw = (rA >> 1) & 3;
        offA[mi] = (uint32_t)(rA*64) + (uint32_t)((h4 ^ sw) << 4);
    }
    #pragma unroll
    for (int p = 0; p < 4; p++){
        int rB = wn*64 + p*16 + h4*8 + l8;
        int sw = (rB >> 1) & 3;
        offB[p] = (uint32_t)(rB*64) + (uint32_t)((h3 ^ sw) << 4);
    }

    float acc[2][8][4];
    #pragma unroll
    for (int i = 0; i < 2; i++)
        #pragma unroll
        for (int j = 0; j < 8; j++)
            #pragma unroll
            for (int r = 0; r < 4; r++) acc[i][j][r] = 0.f;

    auto produce1 = [&](int kc, int st){
        const int r = t >> 2, c = t & 3;
        const int k0 = kc*32 + c*8;
        uint4 av = *(const uint4*)(eaH + (size_t)sSrc[r]*512 + k0);
        const float* pb = ebF + (size_t)sDst[r]*512 + k0;
        float4 e0 = *(const float4*)pb, e1 = *(const float4*)(pb + 4);
        const __half2* ah = (const __half2*)&av;
        float2 f0 = __half22float2(ah[0]), f1 = __half22float2(ah[1]);
        float2 f2 = __half22float2(ah[2]), f3 = __half22float2(ah[3]);
        __half2 h0 = __floats2half2_rn(gelu_exact(f0.x+e0.x), gelu_exact(f0.y+e0.y));
        __half2 h1 = __floats2half2_rn(gelu_exact(f1.x+e0.z), gelu_exact(f1.y+e0.w));
        __half2 h2 = __floats2half2_rn(gelu_exact(f2.x+e1.x), gelu_exact(f2.y+e1.y));
        __half2 h3v = __floats2half2_rn(gelu_exact(f3.x+e1.z), gelu_exact(f3.y+e1.w));
        uint4 pk;
        pk.x = *reinterpret_cast<uint32_t*>(&h0);
        pk.y = *reinterpret_cast<uint32_t*>(&h1);
        pk.z = *reinterpret_cast<uint32_t*>(&h2);
        pk.w = *reinterpret_cast<uint32_t*>(&h3v);
        *(uint4*)(smem + 49152 + st*4096 + r*64 + ((c ^ ((r>>1)&3)) << 4)) = pk;
        #pragma unroll
        for (int it = 0; it < 4; it++){
            const int idx = it*256 + t, rr = idx >> 2, cc = idx & 3;
            uint32_t db = sb + st*16384 + rr*64 + (uint32_t)((cc ^ ((rr>>1)&3)) << 4);
            CP16(db, (const void*)(W2 + (size_t)rr*512 + kc*32 + cc*8));
        }
        CP_COMMIT();
    };

    produce1(0, 0); produce1(1, 1);

    int ccur = 0, pcur = 2;
    #pragma unroll 1
    for (int kc = 0; kc < 16; kc++){
        CP_WAIT1();
        __syncthreads();
        const uint32_t aB = sb + 49152u + ccur*4096;
        const uint32_t bB = sb + ccur*16384;
        #pragma unroll
        for (int s = 0; s < 2; s++){
            const uint32_t sx = (uint32_t)s << 5;
            uint32_t afr[2][4], bfr[8][2];
            #pragma unroll
            for (int mi = 0; mi < 2; mi++)
                ldsm4(afr[mi][0], afr[mi][1], afr[mi][2], afr[mi][3],
                      aB + (offA[mi] ^ sx));
            #pragma unroll
            for (int p = 0; p < 4; p++)
                ldsm4(bfr[2*p][0], bfr[2*p][1], bfr[2*p+1][0], bfr[2*p+1][1],
                      bB + (offB[p] ^ sx));
            #pragma unroll
            for (int mi = 0; mi < 2; mi++)
                #pragma unroll
                for (int nj = 0; nj < 8; nj++)
                    mma16(acc[mi][nj], afr[mi], bfr[nj]);
        }
        if (kc + 2 < 16) produce1(kc + 2, pcur); else CP_COMMIT();
        ccur = (ccur == 2) ? 0 : ccur + 1;
        pcur = (pcur == 2) ? 0 : pcur + 1;
    }

    // ---- epilogue: m2mean[dst] = mean_16( gelu(acc + b2) )
    #pragma unroll
    for (int mi = 0; mi < 2; mi++){
        #pragma unroll
        for (int nj = 0; nj < 8; nj++){
            const int cb = wn*64 + nj*8 + 2*tig;
            const float b0 = b2[cb], b1 = b2[cb+1];
            float s0 = gelu_exact(acc[mi][nj][0] + b0) + gelu_exact(acc[mi][nj][2] + b0);
            float s1 = gelu_exact(acc[mi][nj][1] + b1) + gelu_exact(acc[mi][nj][3] + b1);
            s0 += __shfl_xor_sync(0xffffffffu, s0, 4);
            s0 += __shfl_xor_sync(0xffffffffu, s0, 8);
            s0 += __shfl_xor_sync(0xffffffffu, s0, 16);
            s1 += __shfl_xor_sync(0xffffffffu, s1, 4);
            s1 += __shfl_xor_sync(0xffffffffu, s1, 8);
            s1 += __shfl_xor_sync(0xffffffffu, s1, 16);
            if (lane < 4){
                const int dst = (m0 >> 4) + wm*2 + mi;
                *(__half2*)(m2mean + (size_t)dst*256 + cb) =
                    __floats2half2_rn(s0 * 0.0625f, s1 * 0.0625f);
            }
        }
    }
}

// ---------------------------------------------------------------------------
extern "C" void kernel_launch(void* const* d_in, const int* in_sizes, int n_in,
                              void* d_out, int out_size)
{
    const float* x        = (const float*)d_in[0];
    const float* mesh_pos = (const float*)d_in[1];
    const int*   me32     = (const int*)  d_in[2];
    const float* ip_w1 = (const float*)d_in[4];
    const float* ip_b1 = (const float*)d_in[5];
    const float* ip_w2 = (const float*)d_in[6];
    const float* ip_b2 = (const float*)d_in[7];
    const float* ip_w3 = (const float*)d_in[8];
    const float* ip_b3 = (const float*)d_in[9];
    const float* bf    = (const float*)d_in[10];
    const float* mw1   = (const float*)d_in[11];
    const float* mb1   = (const float*)d_in[12];
    const float* mw2   = (const float*)d_in[13];
    const float* mb2   = (const float*)d_in[14];
    const float* mw3   = (const float*)d_in[15];
    const float* mb3   = (const float*)d_in[16];
    float* out = (float*)d_out;

    __half *m2mp, *hhp, *eaHp, *w2h, *w3h, *mw1h, *mw2h, *mw3h;
    float  *ebp;
    cudaGetSymbolAddress((void**)&m2mp, g_m2m);
    cudaGetSymbolAddress((void**)&hhp,  g_hh);
    cudaGetSymbolAddress((void**)&eaHp, g_eaH);
    cudaGetSymbolAddress((void**)&ebp,  g_eb);
    cudaGetSymbolAddress((void**)&w2h,  g_w2h);
    cudaGetSymbolAddress((void**)&w3h,  g_w3h);
    cudaGetSymbolAddress((void**)&mw1h, g_mw1h);
    cudaGetSymbolAddress((void**)&mw2h, g_mw2h);
    cudaGetSymbolAddress((void**)&mw3h, g_mw3h);

    cudaFuncSetAttribute(gemm16_dual,         cudaFuncAttributeMaxDynamicSharedMemorySize, GEMM_SMEM);
    cudaFuncSetAttribute(gemm16<256,0,true >, cudaFuncAttributeMaxDynamicSharedMemorySize, GEMM_SMEM);
    cudaFuncSetAttribute(node_fused,          cudaFuncAttributeMaxDynamicSharedMemorySize, FUSED_SMEM);
    cudaFuncSetAttribute(edge_fused,          cudaFuncAttributeMaxDynamicSharedMemorySize, EDGE_SMEM);

    // single fp16 weight prep launch (also detects mesh_edges dtype)
    f2h_all<<<576, 256>>>(ip_w2, ip_w3, mw1, mw2, mw3,
                          w2h, w3h, mw1h, mw2h, mw3h, me32);

    // node encoder fully fused: h1 (in-producer) + layers 2,3 (+fourier) -> hh
    node_fused<<<N_NODES/64, 256, FUSED_SMEM>>>(
        x, ip_w1, ip_b1, w2h, ip_b2, w3h, ip_b3, mesh_pos, bf, hhp);

    // hoisted edge layer-1 halves in ONE launch (ea: 4096 blocks, eb: 512)
    gemm16_dual<<<4096 + 512, 256, GEMM_SMEM>>>(hhp, mw1h, mb1, eaHp, ebp);

    // edge layer 2 + segment mean (W3 hoisted past the mean)
    edge_fused<<<N_EDGES/64, 256, EDGE_SMEM>>>(
        eaHp, ebp, mw2h, mb2, m2mp, me32);

    // final: out = m2mean @ W3^T + b3   (16384 x 256, K=256)
    gemm16<256,0,true ><<<dim3(N_DST/128,2), 256, GEMM_SMEM>>>(
        m2mp, 256, mw3h, 256, mb3, out, 256);
}

// round 16
// speedup vs baseline: 1.0721x; 1.0150x over previous
#include <cuda_runtime.h>
#include <cuda_fp16.h>
#include <math.h>
#include <stdint.h>

#define N_NODES 131072
#define N_DST   16384
#define DEG     16
#define N_EDGES (N_DST*DEG)
#define HID     256

// ---------------- global scratch (device globals: no runtime alloc) --------
__device__ __align__(16) __half g_m2m[(size_t)N_DST * 256];     // m2mean
__device__ __align__(16) __half g_hh [(size_t)N_NODES * 256];
__device__ __align__(16) __half g_eaH[(size_t)N_NODES * 512];
__device__ __align__(16) float  g_eb [(size_t)N_DST   * 512];
__device__ __align__(16) __half g_w2h [256*256];
__device__ __align__(16) __half g_w3h [256*256];
__device__ __align__(16) __half g_mw1h[512*512];
__device__ __align__(16) __half g_mw2h[256*512];
__device__ __align__(16) __half g_mw3h[256*256];
__device__ int g_is64;

__device__ __forceinline__ float gelu_exact(float x){
    return 0.5f * x * (1.0f + erff(x * 0.70710678118654752f));
}
__device__ __forceinline__ uint32_t smem_u32(const void* p){
    uint32_t a;
    asm("{ .reg .u64 t; cvta.to.shared.u64 t, %1; cvt.u32.u64 %0, t; }" : "=r"(a) : "l"(p));
    return a;
}
__device__ __forceinline__ void mma16(float* c, const uint32_t* a, const uint32_t* b){
    asm volatile("mma.sync.aligned.m16n8k16.row.col.f32.f16.f16.f32 "
        "{%0,%1,%2,%3}, {%4,%5,%6,%7}, {%8,%9}, {%0,%1,%2,%3};"
        : "+f"(c[0]), "+f"(c[1]), "+f"(c[2]), "+f"(c[3])
        : "r"(a[0]), "r"(a[1]), "r"(a[2]), "r"(a[3]), "r"(b[0]), "r"(b[1]));
}
__device__ __forceinline__ void ldsm4(uint32_t& r0, uint32_t& r1, uint32_t& r2, uint32_t& r3,
                                      uint32_t addr){
    asm volatile("ldmatrix.sync.aligned.m8n8.x4.shared.b16 {%0,%1,%2,%3}, [%4];"
        : "=r"(r0), "=r"(r1), "=r"(r2), "=r"(r3) : "r"(addr));
}
#define CP16(dst, src) \
    asm volatile("cp.async.ca.shared.global [%0], [%1], 16;" :: "r"(dst), "l"(src) : "memory")
#define CP_COMMIT() asm volatile("cp.async.commit_group;" ::: "memory")
#define CP_WAIT2()  asm volatile("cp.async.wait_group 2;"  ::: "memory")
#define CP_WAIT1()  asm volatile("cp.async.wait_group 1;"  ::: "memory")

// ---------------------------------------------------------------------------
// one-shot fp16 conversion of all five weight matrices + edge-dtype detect
__global__ __launch_bounds__(256)
void f2h_all(const float* __restrict__ w2, const float* __restrict__ w3,
             const float* __restrict__ m1, const float* __restrict__ m2,
             const float* __restrict__ m3,
             __half* __restrict__ dw2, __half* __restrict__ dw3,
             __half* __restrict__ dm1, __half* __restrict__ dm2,
             __half* __restrict__ dm3, const int* __restrict__ me32)
{
    int i = blockIdx.x*256 + threadIdx.x;          // float4 index, total 147456
    if (i == 0) g_is64 = (me32[32] != 1) ? 1 : 0;
    const float* s; __half* d; int off;
    if      (i <  16384){ s = w2; d = dw2; off = i; }
    else if (i <  32768){ s = w3; d = dw3; off = i - 16384; }
    else if (i <  98304){ s = m1; d = dm1; off = i - 32768; }
    else if (i < 131072){ s = m2; d = dm2; off = i - 98304; }
    else                { s = m3; d = dm3; off = i - 131072; }
    float4 v = ((const float4*)s)[off];
    __half2 h0 = __floats2half2_rn(v.x, v.y), h1 = __floats2half2_rn(v.z, v.w);
    uint2 pk;
    pk.x = *reinterpret_cast<uint32_t*>(&h0);
    pk.y = *reinterpret_cast<uint32_t*>(&h1);
    ((uint2*)d)[off] = pk;
}

// ---------------------------------------------------------------------------
// fp16 mma.sync GEMM (R11 proven): block 128x128, BK=32, 8 warps (4m x 2n),
// warp tile 32x64, 4-stage cp.async, 64KB smem, 2 CTAs/SM.
// EPI: 0=fp32 store(+bias), 4=plain fp16.
// ---------------------------------------------------------------------------
#define GEMM_SMEM (64*1024)

template<int K, int EPI, bool HAS_BIAS>
__global__ __launch_bounds__(256, 2)
void gemm16(const __half* __restrict__ A, int lda,
            const __half* __restrict__ W, int ldw,
            const float* __restrict__ bias,
            void* __restrict__ Cout, int ldc)
{
    extern __shared__ char smem[];
    const int t    = threadIdx.x;
    const int lane = t & 31;
    const int w    = t >> 5;
    const int wm   = w >> 1, wn = w & 1;
    const int gid  = lane >> 2, tig = lane & 3;
    const int m0   = blockIdx.x * 128;
    const int n0   = blockIdx.y * 128;
    const uint32_t sb = smem_u32(smem);

    uint32_t offA[2], offB[4];
    {
        const int l8 = lane & 7;
        const int h3 = (lane >> 3) & 1;
        const int h4 = lane >> 4;
        #pragma unroll
        for (int mi = 0; mi < 2; mi++){
            int rA = wm*32 + mi*16 + h3*8 + l8;
            int sw = (rA >> 1) & 3;
            offA[mi] = (uint32_t)(rA*64) + (uint32_t)((h4 ^ sw) << 4);
        }
        #pragma unroll
        for (int p = 0; p < 4; p++){
            int rB = wn*64 + p*16 + h4*8 + l8;
            int sw = (rB >> 1) & 3;
            offB[p] = (uint32_t)(rB*64) + (uint32_t)((h3 ^ sw) << 4);
        }
    }

    float acc[2][8][4];
    #pragma unroll
    for (int i = 0; i < 2; i++)
        #pragma unroll
        for (int j = 0; j < 8; j++)
            #pragma unroll
            for (int r = 0; r < 4; r++) acc[i][j][r] = 0.f;

    constexpr int NC = K / 32;

    auto produce = [&](int kc){
        const int st = kc & 3;
        #pragma unroll
        for (int it = 0; it < 2; it++){
            const int idx = it*256 + t, r = idx >> 2, c = idx & 3;
            uint32_t dst = sb + st*8192 + r*64 + (uint32_t)((c ^ ((r>>1)&3)) << 4);
            CP16(dst, (const void*)(A + (size_t)(m0 + r)*lda + kc*32 + c*8));
        }
        #pragma unroll
        for (int it = 0; it < 2; it++){
            const int idx = it*256 + t, rr = idx >> 2, cc = idx & 3;
            uint32_t db = sb + 32768 + st*8192 + rr*64 + (uint32_t)((cc ^ ((rr>>1)&3)) << 4);
            CP16(db, (const void*)(W + (size_t)(n0 + rr)*ldw + kc*32 + cc*8));
        }
        CP_COMMIT();
    };

    produce(0); produce(1); produce(2);

    #pragma unroll 1
    for (int kc = 0; kc < NC; kc++){
        CP_WAIT2();
        __syncthreads();
        const uint32_t aB = sb + (kc & 3)*8192;
        const uint32_t bB = sb + 32768u + (kc & 3)*8192;
        #pragma unroll
        for (int s = 0; s < 2; s++){
            const uint32_t sx = (uint32_t)s << 5;
            uint32_t afr[2][4], bfr[8][2];
            #pragma unroll
            for (int mi = 0; mi < 2; mi++)
                ldsm4(afr[mi][0], afr[mi][1], afr[mi][2], afr[mi][3],
                      aB + (offA[mi] ^ sx));
            #pragma unroll
            for (int p = 0; p < 4; p++)
                ldsm4(bfr[2*p][0], bfr[2*p][1], bfr[2*p+1][0], bfr[2*p+1][1],
                      bB + (offB[p] ^ sx));
            #pragma unroll
            for (int mi = 0; mi < 2; mi++)
                #pragma unroll
                for (int nj = 0; nj < 8; nj++)
                    mma16(acc[mi][nj], afr[mi], bfr[nj]);
        }
        if (kc + 3 < NC) produce(kc + 3); else CP_COMMIT();
    }

    #pragma unroll
    for (int mi = 0; mi < 2; mi++){
        const int r0 = m0 + wm*32 + mi*16 + gid;
        const int r1 = r0 + 8;
        #pragma unroll
        for (int nj = 0; nj < 8; nj++){
            const int cb = n0 + wn*64 + nj*8 + 2*tig;
            float v0 = acc[mi][nj][0], v1 = acc[mi][nj][1];
            float v2 = acc[mi][nj][2], v3 = acc[mi][nj][3];
            if (HAS_BIAS){
                const float b0 = bias[cb], b1 = bias[cb+1];
                v0 += b0; v1 += b1; v2 += b0; v3 += b1;
            }
            if (EPI == 0){
                float* C = (float*)Cout;
                *(float2*)(C + (size_t)r0*ldc + cb) = make_float2(v0, v1);
                *(float2*)(C + (size_t)r1*ldc + cb) = make_float2(v2, v3);
            } else {
                __half* C = (__half*)Cout;
                *(__half2*)(C + (size_t)r0*ldc + cb) = __floats2half2_rn(v0, v1);
                *(__half2*)(C + (size_t)r1*ldc + cb) = __floats2half2_rn(v2, v3);
            }
        }
    }
}

// ---------------------------------------------------------------------------
// Fused node-encoder kernel (R11 proven), 2 CTAs/SM, 64 nodes/block.
// ---------------------------------------------------------------------------
#define FUSED_SMEM (64*1024)

__global__ __launch_bounds__(256, 2)
void node_fused(const float* __restrict__ xg,
                const float* __restrict__ w1g, const float* __restrict__ b1g,
                const __half* __restrict__ W2, const float* __restrict__ b2,
                const __half* __restrict__ W3, const float* __restrict__ b3,
                const float* __restrict__ pos, const float* __restrict__ bfour,
                __half* __restrict__ hh)
{
    extern __shared__ char smem[];
    __shared__ float sX[64*3];
    __shared__ float sW1[256*3];
    __shared__ float sB1[256];
    const int t    = threadIdx.x;
    const int lane = t & 31;
    const int w    = t >> 5;
    const int wm   = w >> 2, wn = w & 3;
    const int gid  = lane >> 2, tig = lane & 3;
    const int m0   = blockIdx.x * 64;
    const uint32_t sb = smem_u32(smem);

    if (t < 192) sX[t] = xg[(size_t)m0*3 + t];
    for (int i = t; i < 768; i += 256) sW1[i] = w1g[i];
    sB1[t] = b1g[t];
    __syncthreads();

    uint32_t offA[2], offB[4], baseM[2];
    int swM[2];
    const int l8 = lane & 7;
    const int h3 = (lane >> 3) & 1;
    const int h4 = lane >> 4;
    #pragma unroll
    for (int mi = 0; mi < 2; mi++){
        int rA = wm*32 + mi*16 + h3*8 + l8;
        int sw = (rA >> 1) & 3;
        offA[mi] = (uint32_t)(rA*64) + (uint32_t)((h4 ^ sw) << 4);
        baseM[mi] = (uint32_t)(rA*512);
        swM[mi] = rA & 7;
    }
    #pragma unroll
    for (int p = 0; p < 4; p++){
        int rB = wn*64 + p*16 + h4*8 + l8;
        int sw = (rB >> 1) & 3;
        offB[p] = (uint32_t)(rB*64) + (uint32_t)((h3 ^ sw) << 4);
    }

    float acc[2][8][4];
    #pragma unroll
    for (int i = 0; i < 2; i++)
        #pragma unroll
        for (int j = 0; j < 8; j++)
            #pragma unroll
            for (int r = 0; r < 4; r++) acc[i][j][r] = 0.f;

    auto produce1 = [&](int kc, int st){
        const int r = t >> 2, c = t & 3;
        const int j0 = kc*32 + c*8;
        const float x0 = sX[r*3], x1 = sX[r*3+1], x2 = sX[r*3+2];
        uint4 pk;
        uint32_t* pw = (uint32_t*)&pk;
        #pragma unroll
        for (int jj = 0; jj < 4; jj++){
            const int ja = j0 + 2*jj, jb = ja + 1;
            float va = fmaf(x0, sW1[ja*3], fmaf(x1, sW1[ja*3+1], fmaf(x2, sW1[ja*3+2], sB1[ja])));
            float vb = fmaf(x0, sW1[jb*3], fmaf(x1, sW1[jb*3+1], fmaf(x2, sW1[jb*3+2], sB1[jb])));
            __half2 hv = __floats2half2_rn(gelu_exact(va), gelu_exact(vb));
            pw[jj] = *reinterpret_cast<uint32_t*>(&hv);
        }
        *(uint4*)(smem + 49152 + st*4096 + r*64 + ((c ^ ((r>>1)&3)) << 4)) = pk;
        #pragma unroll
        for (int it = 0; it < 4; it++){
            const int idx = it*256 + t, rr = idx >> 2, cc = idx & 3;
            uint32_t db = sb + st*16384 + rr*64 + (uint32_t)((cc ^ ((rr>>1)&3)) << 4);
            CP16(db, (const void*)(W2 + (size_t)rr*256 + kc*32 + cc*8));
        }
        CP_COMMIT();
    };

    produce1(0, 0); produce1(1, 1);

    int ccur = 0, pcur = 2;
    #pragma unroll 1
    for (int kc = 0; kc < 8; kc++){
        CP_WAIT1();
        __syncthreads();
        const uint32_t aB = sb + 49152u + ccur*4096;
        const uint32_t bB = sb + ccur*16384;
        #pragma unroll
        for (int s = 0; s < 2; s++){
            const uint32_t sx = (uint32_t)s << 5;
            uint32_t afr[2][4], bfr[8][2];
            #pragma unroll
            for (int mi = 0; mi < 2; mi++)
                ldsm4(afr[mi][0], afr[mi][1], afr[mi][2], afr[mi][3],
                      aB + (offA[mi] ^ sx));
            #pragma unroll
            for (int p = 0; p < 4; p++)
                ldsm4(bfr[2*p][0], bfr[2*p][1], bfr[2*p+1][0], bfr[2*p+1][1],
                      bB + (offB[p] ^ sx));
            #pragma unroll
            for (int mi = 0; mi < 2; mi++)
                #pragma unroll
                for (int nj = 0; nj < 8; nj++)
                    mma16(acc[mi][nj], afr[mi], bfr[nj]);
        }
        if (kc + 2 < 8) produce1(kc + 2, pcur); else CP_COMMIT();
        ccur = (ccur == 2) ? 0 : ccur + 1;
        pcur = (pcur == 2) ? 0 : pcur + 1;
    }

    __syncthreads();

    auto produce2 = [&](int kc){
        const int st = kc & 1;
        #pragma unroll
        for (int it = 0; it < 4; it++){
            const int idx = it*256 + t, rr = idx >> 2, cc = idx & 3;
            uint32_t db = sb + 32768 + st*16384 + rr*64 + (uint32_t)((cc ^ ((rr>>1)&3)) << 4);
            CP16(db, (const void*)(W3 + (size_t)rr*256 + kc*32 + cc*8));
        }
        CP_COMMIT();
    };
    produce2(0);

    #pragma unroll
    for (int mi = 0; mi < 2; mi++){
        const int lr0 = wm*32 + mi*16 + gid;
        const int lr1 = lr0 + 8;
        #pragma unroll
        for (int nj = 0; nj < 8; nj++){
            const int cb = wn*64 + nj*8 + 2*tig;
            const float b0 = b2[cb], b1 = b2[cb+1];
            __half2 lo = __floats2half2_rn(gelu_exact(acc[mi][nj][0] + b0),
                                           gelu_exact(acc[mi][nj][1] + b1));
            __half2 hi = __floats2half2_rn(gelu_exact(acc[mi][nj][2] + b0),
                                           gelu_exact(acc[mi][nj][3] + b1));
            const int blk = cb >> 3;
            *(__half2*)(smem + lr0*512 + ((blk ^ (lr0 & 7)) << 4) + 4*tig) = lo;
            *(__half2*)(smem + lr1*512 + ((blk ^ (lr1 & 7)) << 4) + 4*tig) = hi;
            acc[mi][nj][0] = 0.f; acc[mi][nj][1] = 0.f;
            acc[mi][nj][2] = 0.f; acc[mi][nj][3] = 0.f;
        }
    }

    #pragma unroll 1
    for (int kc = 0; kc < 8; kc++){
        __syncthreads();
        if (kc + 1 < 8) produce2(kc + 1); else CP_COMMIT();
        CP_WAIT1();
        __syncthreads();
        const uint32_t bB = sb + 32768u + (kc & 1)*16384;
        #pragma unroll
        for (int s = 0; s < 2; s++){
            const uint32_t sx = (uint32_t)s << 5;
            uint32_t afr[2][4], bfr[8][2];
            #pragma unroll
            for (int mi = 0; mi < 2; mi++){
                const int blk = kc*4 + h4;
                const uint32_t offM = (uint32_t)((blk ^ swM[mi]) << 4);
                ldsm4(afr[mi][0], afr[mi][1], afr[mi][2], afr[mi][3],
                      sb + baseM[mi] + (offM ^ sx));
            }
            #pragma unroll
            for (int p = 0; p < 4; p++)
                ldsm4(bfr[2*p][0], bfr[2*p][1], bfr[2*p+1][0], bfr[2*p+1][1],
                      bB + (offB[p] ^ sx));
            #pragma unroll
            for (int mi = 0; mi < 2; mi++)
                #pragma unroll
                for (int nj = 0; nj < 8; nj++)
                    mma16(acc[mi][nj], afr[mi], bfr[nj]);
        }
    }

    #pragma unroll
    for (int mi = 0; mi < 2; mi++){
        const int r0 = m0 + wm*32 + mi*16 + gid;
        const int r1 = r0 + 8;
        const float p00 = pos[(size_t)r0*2], p01 = pos[(size_t)r0*2 + 1];
        const float p10 = pos[(size_t)r1*2], p11 = pos[(size_t)r1*2 + 1];
        #pragma unroll
        for (int nj = 0; nj < 8; nj++){
            const int cb = wn*64 + nj*8 + 2*tig;
            const float b0 = b3[cb], b1 = b3[cb+1];
            float v0 = acc[mi][nj][0] + b0, v1 = acc[mi][nj][1] + b1;
            float v2 = acc[mi][nj][2] + b0, v3 = acc[mi][nj][3] + b1;
            const int o0 = cb, o1 = cb + 1;
            const float ba0 = bfour[(o0 & 127)*2], bb0 = bfour[(o0 & 127)*2 + 1];
            const float ba1 = bfour[(o1 & 127)*2], bb1 = bfour[(o1 & 127)*2 + 1];
            const float TP = 6.283185307179586f;
            float pl0 = TP*(p00*ba0 + p01*bb0), pl1 = TP*(p00*ba1 + p01*bb1);
            float ph0 = TP*(p10*ba0 + p11*bb0), ph1 = TP*(p10*ba1 + p11*bb1);
            v0 += (o0 < 128) ? __cosf(pl0) : __sinf(pl0);
            v1 += (o1 < 128) ? __cosf(pl1) : __sinf(pl1);
            v2 += (o0 < 128) ? __cosf(ph0) : __sinf(ph0);
            v3 += (o1 < 128) ? __cosf(ph1) : __sinf(ph1);
            *(__half2*)(hh + (size_t)r0*256 + cb) = __floats2half2_rn(v0, v1);
            *(__half2*)(hh + (size_t)r1*256 + cb) = __floats2half2_rn(v2, v3);
        }
    }
}

// ---------------------------------------------------------------------------
// Edge kernel (R10 geometry, strength-reduced producer addressing):
// 64 edges (= 4 dsts) per block, 2 CTAs/SM:
//   m2 = gelu([gelu(ea[src]+eb[dst])] @ W2^T + b2)   (K=512)
//   m2mean[dst] = mean_16(m2)  -> gmem fp16
// SMEM 64KB: W2 3x16KB [0,48K), A 3x4KB [48K,60K).
// Producer bases (pA/pB/pW0/swz) hoisted: per-chunk address math is +kc*32,
// +st*4096/16384, +it*{4096 smem, 32768 gmem} only.
// ---------------------------------------------------------------------------
#define EDGE_SMEM (64*1024)

__global__ __launch_bounds__(256, 2)
void edge_fused(const __half* __restrict__ eaH, const float* __restrict__ ebF,
                const __half* __restrict__ W2, const float* __restrict__ b2,
                __half* __restrict__ m2mean, const int* __restrict__ me32)
{
    extern __shared__ char smem[];
    __shared__ int sSrc[64], sDst[64];
    const int t    = threadIdx.x;
    const int lane = t & 31;
    const int w    = t >> 5;
    const int wm   = w >> 2, wn = w & 3;
    const int tig  = lane & 3;
    const int m0   = blockIdx.x * 64;
    const uint32_t sb = smem_u32(smem);

    if (t < 64){
        const int e = m0 + t; int s, d;
        if (g_is64){ d = me32[4*e]; s = me32[4*e+2]; }
        else       { d = me32[2*e]; s = me32[2*e+1]; }
        sSrc[t] = s; sDst[t] = d;
    }
    __syncthreads();

    // ---- hoisted producer bases (thread-constant) ----
    const int r = t >> 2, c = t & 3;
    const __half* pA  = eaH + (size_t)sSrc[r]*512 + c*8;
    const float*  pB  = ebF + (size_t)sDst[r]*512 + c*8;
    const __half* pW0 = W2  + (size_t)r*512 + c*8;
    const uint32_t swz = (uint32_t)(r*64) + (uint32_t)((c ^ ((r>>1)&3)) << 4);
    char* stsA0        = smem + 49152 + swz;   // A-tile STS base (add st*4096)
    const uint32_t dbW0 = sb + swz;            // W2 cp.async base (add st*16384 + it*4096)

    // per-lane ldmatrix offsets
    uint32_t offA[2], offB[4];
    const int l8 = lane & 7;
    const int h3 = (lane >> 3) & 1;
    const int h4 = lane >> 4;
    #pragma unroll
    for (int mi = 0; mi < 2; mi++){
        int rA = wm*32 + mi*16 + h3*8 + l8;
        int sw = (rA >> 1) & 3;
        offA[mi] = (uint32_t)(rA*64) + (uint32_t)((h4 ^ sw) << 4);
    }
    #pragma unroll
    for (int p = 0; p < 4; p++){
        int rB = wn*64 + p*16 + h4*8 + l8;
        int sw = (rB >> 1) & 3;
        offB[p] = (uint32_t)(rB*64) + (uint32_t)((h3 ^ sw) << 4);
    }

    float acc[2][8][4];
    #pragma unroll
    for (int i = 0; i < 2; i++)
        #pragma unroll
        for (int j = 0; j < 8; j++)
            #pragma unroll
            for (int r2 = 0; r2 < 4; r2++) acc[i][j][r2] = 0.f;

    // ---- producer: A = gelu(ea[src]+eb[dst]) (STS), B = W2 (cp.async)
    auto produce1 = [&](int kc, int st){
        const int k0 = kc*32;
        uint4 av = *(const uint4*)(pA + k0);
        float4 e0 = *(const float4*)(pB + k0);
        float4 e1 = *(const float4*)(pB + k0 + 4);
        const __half2* ah = (const __half2*)&av;
        float2 f0 = __half22float2(ah[0]), f1 = __half22float2(ah[1]);
        float2 f2 = __half22float2(ah[2]), f3 = __half22float2(ah[3]);
        __half2 h0 = __floats2half2_rn(gelu_exact(f0.x+e0.x), gelu_exact(f0.y+e0.y));
        __half2 h1 = __floats2half2_rn(gelu_exact(f1.x+e0.z), gelu_exact(f1.y+e0.w));
        __half2 h2 = __floats2half2_rn(gelu_exact(f2.x+e1.x), gelu_exact(f2.y+e1.y));
        __half2 h3v = __floats2half2_rn(gelu_exact(f3.x+e1.z), gelu_exact(f3.y+e1.w));
        uint4 pk;
        pk.x = *reinterpret_cast<uint32_t*>(&h0);
        pk.y = *reinterpret_cast<uint32_t*>(&h1);
        pk.z = *reinterpret_cast<uint32_t*>(&h2);
        pk.w = *reinterpret_cast<uint32_t*>(&h3v);
        *(uint4*)(stsA0 + st*4096) = pk;
        const uint32_t dbs = dbW0 + (uint32_t)(st*16384);
        #pragma unroll
        for (int it = 0; it < 4; it++)
            CP16(dbs + (uint32_t)(it*4096), (const void*)(pW0 + it*32768 + k0));
        CP_COMMIT();
    };

    produce1(0, 0); produce1(1, 1);

    int ccur = 0, pcur = 2;
    #pragma unroll 1
    for (int kc = 0; kc < 16; kc++){
        CP_WAIT1();
        __syncthreads();
        const uint32_t aB = sb + 49152u + ccur*4096;
        const uint32_t bB = sb + ccur*16384;
        #pragma unroll
        for (int s = 0; s < 2; s++){
            const uint32_t sx = (uint32_t)s << 5;
            uint32_t afr[2][4], bfr[8][2];
            #pragma unroll
            for (int mi = 0; mi < 2; mi++)
                ldsm4(afr[mi][0], afr[mi][1], afr[mi][2], afr[mi][3],
                      aB + (offA[mi] ^ sx));
            #pragma unroll
            for (int p = 0; p < 4; p++)
                ldsm4(bfr[2*p][0], bfr[2*p][1], bfr[2*p+1][0], bfr[2*p+1][1],
                      bB + (offB[p] ^ sx));
            #pragma unroll
            for (int mi = 0; mi < 2; mi++)
                #pragma unroll
                for (int nj = 0; nj < 8; nj++)
                    mma16(acc[mi][nj], afr[mi], bfr[nj]);
        }
        if (kc + 2 < 16) produce1(kc + 2, pcur); else CP_COMMIT();
        ccur = (ccur == 2) ? 0 : ccur + 1;
        pcur = (pcur == 2) ? 0 : pcur + 1;
    }

    // ---- epilogue: m2mean[dst] = mean_16( gelu(acc + b2) )
    #pragma unroll
    for (int mi = 0; mi < 2; mi++){
        #pragma unroll
        for (int nj = 0; nj < 8; nj++){
            const int cb = wn*64 + nj*8 + 2*tig;
            const float b0 = b2[cb], b1 = b2[cb+1];
            float s0 = gelu_exact(acc[mi][nj][0] + b0) + gelu_exact(acc[mi][nj][2] + b0);
            float s1 = gelu_exact(acc[mi][nj][1] + b1) + gelu_exact(acc[mi][nj][3] + b1);
            s0 += __shfl_xor_sync(0xffffffffu, s0, 4);
            s0 += __shfl_xor_sync(0xffffffffu, s0, 8);
            s0 += __shfl_xor_sync(0xffffffffu, s0, 16);
            s1 += __shfl_xor_sync(0xffffffffu, s1, 4);
            s1 += __shfl_xor_sync(0xffffffffu, s1, 8);
            s1 += __shfl_xor_sync(0xffffffffu, s1, 16);
            if (lane < 4){
                const int dst = (m0 >> 4) + wm*2 + mi;
                *(__half2*)(m2mean + (size_t)dst*256 + cb) =
                    __floats2half2_rn(s0 * 0.0625f, s1 * 0.0625f);
            }
        }
    }
}

// ---------------------------------------------------------------------------
extern "C" void kernel_launch(void* const* d_in, const int* in_sizes, int n_in,
                              void* d_out, int out_size)
{
    const float* x        = (const float*)d_in[0];
    const float* mesh_pos = (const float*)d_in[1];
    const int*   me32     = (const int*)  d_in[2];
    const float* ip_w1 = (const float*)d_in[4];
    const float* ip_b1 = (const float*)d_in[5];
    const float* ip_w2 = (const float*)d_in[6];
    const float* ip_b2 = (const float*)d_in[7];
    const float* ip_w3 = (const float*)d_in[8];
    const float* ip_b3 = (const float*)d_in[9];
    const float* bf    = (const float*)d_in[10];
    const float* mw1   = (const float*)d_in[11];
    const float* mb1   = (const float*)d_in[12];
    const float* mw2   = (const float*)d_in[13];
    const float* mb2   = (const float*)d_in[14];
    const float* mw3   = (const float*)d_in[15];
    const float* mb3   = (const float*)d_in[16];
    float* out = (float*)d_out;

    __half *m2mp, *hhp, *eaHp, *w2h, *w3h, *mw1h, *mw2h, *mw3h;
    float  *ebp;
    cudaGetSymbolAddress((void**)&m2mp, g_m2m);
    cudaGetSymbolAddress((void**)&hhp,  g_hh);
    cudaGetSymbolAddress((void**)&eaHp, g_eaH);
    cudaGetSymbolAddress((void**)&ebp,  g_eb);
    cudaGetSymbolAddress((void**)&w2h,  g_w2h);
    cudaGetSymbolAddress((void**)&w3h,  g_w3h);
    cudaGetSymbolAddress((void**)&mw1h, g_mw1h);
    cudaGetSymbolAddress((void**)&mw2h, g_mw2h);
    cudaGetSymbolAddress((void**)&mw3h, g_mw3h);

    cudaFuncSetAttribute(gemm16<256,4,false>, cudaFuncAttributeMaxDynamicSharedMemorySize, GEMM_SMEM);
    cudaFuncSetAttribute(gemm16<256,0,true >, cudaFuncAttributeMaxDynamicSharedMemorySize, GEMM_SMEM);
    cudaFuncSetAttribute(node_fused,          cudaFuncAttributeMaxDynamicSharedMemorySize, FUSED_SMEM);
    cudaFuncSetAttribute(edge_fused,          cudaFuncAttributeMaxDynamicSharedMemorySize, EDGE_SMEM);

    // single fp16 weight prep launch (also detects mesh_edges dtype)
    f2h_all<<<576, 256>>>(ip_w2, ip_w3, mw1, mw2, mw3,
                          w2h, w3h, mw1h, mw2h, mw3h, me32);

    // node encoder fully fused: h1 (in-producer) + layers 2,3 (+fourier) -> hh
    node_fused<<<N_NODES/64, 256, FUSED_SMEM>>>(
        x, ip_w1, ip_b1, w2h, ip_b2, w3h, ip_b3, mesh_pos, bf, hhp);

    // hoisted edge layer-1 halves: ea fp16 (no bias), eb fp32 (+b1)
    gemm16<256,4,false><<<dim3(N_NODES/128,4), 256, GEMM_SMEM>>>(
        hhp, 256, mw1h, 512, nullptr, eaHp, 512);
    gemm16<256,0,true ><<<dim3(N_DST/128,4), 256, GEMM_SMEM>>>(
        hhp, 256, mw1h + 256, 512, mb1, ebp, 512);

    // edge layer 2 + segment mean (W3 hoisted past the mean)
    edge_fused<<<N_EDGES/64, 256, EDGE_SMEM>>>(
        eaHp, ebp, mw2h, mb2, m2mp, me32);

    // final: out = m2mean @ W3^T + b3   (16384 x 256, K=256)
    gemm16<256,0,true ><<<dim3(N_DST/128,2), 256, GEMM_SMEM>>>(
        m2mp, 256, mw3h, 256, mb3, out, 256);
}